// round 1
// baseline (speedup 1.0000x reference)
#include <cuda_runtime.h>
#include <math.h>

// Problem constants (B=1024, R=10, L=512)
#define BB   1024
#define RR   10
#define LL   512
#define KK   1024      // 2L
#define BRD  10240     // B*R

// GEMM tiling
#define BM 128
#define BN 128
#define BK 16
#define NCHUNK 8       // 512 / 64 l-values per block

// Scratch (static device memory; no allocation allowed)
__device__ float g_tpart[2][BRD][NCHUNK];  // per-row partial weighted sums
__device__ float g_wvec[2][LL];            // [0]=wh=W1[:L]@W2 (hist), [1]=wq=W1[L:]@W2 (ques)
__device__ float g_c0;                     // b1.W2 + b2

// ---------------------------------------------------------------------------
// Prep: wh, wq, c0
// ---------------------------------------------------------------------------
__global__ void prep_kernel(const float* __restrict__ W1, const float* __restrict__ b1,
                            const float* __restrict__ W2, const float* __restrict__ b2)
{
    int l = threadIdx.x;   // 0..511
    float s0 = 0.f, s1 = 0.f;
    for (int m = 0; m < LL; m++) {
        float w2 = W2[m];
        s0 += W1[(size_t)l * LL + m] * w2;
        s1 += W1[(size_t)(l + LL) * LL + m] * w2;
    }
    g_wvec[0][l] = s0;
    g_wvec[1][l] = s1;
    if (l == 0) {
        float c = 0.f;
        for (int m = 0; m < LL; m++) c += b1[m] * W2[m];
        g_c0 = c + b2[0];
    }
}

// ---------------------------------------------------------------------------
// Fused gated-transform GEMM + weighted reduction.
// Block: computes 128 rows x 64 l-values: u = X@Wy (cols l0..l0+63) and
// v = X@Wg (same l's), then per-row sum of tanh(u+by)*sigmoid(v+bg)*w.
// grid = (M/128, 512/64, 2 inputs)
// ---------------------------------------------------------------------------
__global__ __launch_bounds__(256)
void gemm_kernel(const float* __restrict__ hist, const float* __restrict__ ques,
                 const float* __restrict__ Wy_h, const float* __restrict__ by_h,
                 const float* __restrict__ Wg_h, const float* __restrict__ bg_h,
                 const float* __restrict__ Wy_q, const float* __restrict__ by_q,
                 const float* __restrict__ Wg_q, const float* __restrict__ bg_q)
{
    __shared__ float As[BK][BM];
    __shared__ float Bs[BK][BN];

    const int input = blockIdx.z;
    const int l0    = blockIdx.y * 64;
    const int m0    = blockIdx.x * BM;

    const float* X  = input ? ques : hist;
    const float* Wy = input ? Wy_q : Wy_h;
    const float* Wg = input ? Wg_q : Wg_h;
    const float* by = input ? by_q : by_h;
    const float* bg = input ? bg_q : bg_h;

    const int tid = threadIdx.x;
    const int tx  = tid & 15;     // 0..15 (column group)
    const int ty  = tid >> 4;     // 0..15 (row group)

    float acc[8][8];
    #pragma unroll
    for (int i = 0; i < 8; i++)
        #pragma unroll
        for (int j = 0; j < 8; j++) acc[i][j] = 0.f;

    for (int k0 = 0; k0 < KK; k0 += BK) {
        // ---- load X tile (transpose to As[k][m]) ----
        #pragma unroll
        for (int qq = 0; qq < 2; qq++) {
            int q   = tid * 2 + qq;       // 0..511
            int row = q >> 2;             // 0..127
            int kq  = q & 3;              // 0..3 (quad of k)
            float4 v = *(const float4*)&X[(size_t)(m0 + row) * KK + k0 + kq * 4];
            As[kq * 4 + 0][row] = v.x;
            As[kq * 4 + 1][row] = v.y;
            As[kq * 4 + 2][row] = v.z;
            As[kq * 4 + 3][row] = v.w;
        }
        // ---- load weight tile: cols [0,64) from Wy(l0..), cols [64,128) from Wg(l0..) ----
        #pragma unroll
        for (int qq = 0; qq < 2; qq++) {
            int q  = tid * 2 + qq;        // 0..511
            int k  = q >> 5;              // 0..15
            int j4 = q & 31;              // 0..31
            int j  = j4 * 4;              // 0..124
            const float* src = (j < 64)
                ? &Wy[(size_t)(k0 + k) * LL + l0 + j]
                : &Wg[(size_t)(k0 + k) * LL + l0 + (j - 64)];
            *(float4*)&Bs[k][j] = *(const float4*)src;
        }
        __syncthreads();

        #pragma unroll
        for (int k = 0; k < BK; k++) {
            float a[8], b[8];
            *(float4*)&a[0] = *(const float4*)&As[k][ty * 8];
            *(float4*)&a[4] = *(const float4*)&As[k][ty * 8 + 4];
            *(float4*)&b[0] = *(const float4*)&Bs[k][tx * 4];        // u-part (Wy)
            *(float4*)&b[4] = *(const float4*)&Bs[k][64 + tx * 4];   // v-part (Wg)
            #pragma unroll
            for (int i = 0; i < 8; i++)
                #pragma unroll
                for (int j = 0; j < 8; j++)
                    acc[i][j] += a[i] * b[j];
        }
        __syncthreads();
    }

    // ---- epilogue: tanh(u+by)*sigmoid(v+bg)*w, partial sum over this thread's 4 l's ----
    const int gl = l0 + tx * 4;
    const float* w = g_wvec[input];
    float wv[4], byv[4], bgv[4];
    #pragma unroll
    for (int c = 0; c < 4; c++) {
        wv[c]  = w[gl + c];
        byv[c] = by[gl + c];
        bgv[c] = bg[gl + c];
    }
    float part[8];
    #pragma unroll
    for (int i = 0; i < 8; i++) {
        float s = 0.f;
        #pragma unroll
        for (int c = 0; c < 4; c++) {
            float u = acc[i][c]     + byv[c];
            float v = acc[i][4 + c] + bgv[c];
            s += tanhf(u) * (1.f / (1.f + expf(-v))) * wv[c];
        }
        part[i] = s;
    }

    // ---- deterministic cross-thread reduction (16 column-groups per row) ----
    float* red = &As[0][0];   // reuse smem (2048 floats)
    #pragma unroll
    for (int i = 0; i < 8; i++) red[tx * BM + ty * 8 + i] = part[i];
    __syncthreads();
    if (tx == 0) {
        #pragma unroll
        for (int i = 0; i < 8; i++) {
            float s = 0.f;
            #pragma unroll
            for (int x = 0; x < 16; x++) s += red[x * BM + ty * 8 + i];
            g_tpart[input][m0 + ty * 8 + i][blockIdx.y] = s;
        }
    }
}

// ---------------------------------------------------------------------------
// Final: logits + Gumbel, argmax over prefix, one-hot write.
// ---------------------------------------------------------------------------
__global__ void final_kernel(const float* __restrict__ noise,
                             const float* __restrict__ Wa, const float* __restrict__ ba,
                             float* __restrict__ out)
{
    int t = blockIdx.x * blockDim.x + threadIdx.x;
    if (t >= BRD) return;
    int b = t / RR;
    int i = t % RR;

    float Wa0 = Wa[0], Wa1 = Wa[1], ba0 = ba[0], c0 = g_c0;

    float tq = 0.f;
    #pragma unroll
    for (int c = 0; c < NCHUNK; c++) tq += g_tpart[1][t][c];

    float best = -3.4e38f;
    int bj = 0;
    for (int j = 0; j <= i; j++) {
        float th = 0.f;
        #pragma unroll
        for (int c = 0; c < NCHUNK; c++) th += g_tpart[0][b * RR + j][c];
        float score = tq + th + c0;
        float logit = score * Wa0 + (float)(i - j + 1) * Wa1 + ba0;
        float ns = noise[(size_t)b * RR * RR + i * RR + j];
        float g  = -logf(1e-10f - logf(ns + 1e-10f));
        float z  = logit + g;
        if (z > best) { best = z; bj = j; }   // strict > keeps first max (matches argmax)
    }

    float* o = out + (size_t)b * RR * RR + (size_t)i * RR;
    #pragma unroll
    for (int j = 0; j < RR; j++) o[j] = (j == bj) ? 1.f : 0.f;
}

// ---------------------------------------------------------------------------
extern "C" void kernel_launch(void* const* d_in, const int* in_sizes, int n_in,
                              void* d_out, int out_size)
{
    const float* hist  = (const float*)d_in[0];
    const float* ques  = (const float*)d_in[1];
    const float* noise = (const float*)d_in[2];
    const float* Wy_h  = (const float*)d_in[3];
    const float* by_h  = (const float*)d_in[4];
    const float* Wg_h  = (const float*)d_in[5];
    const float* bg_h  = (const float*)d_in[6];
    const float* Wy_q  = (const float*)d_in[7];
    const float* by_q  = (const float*)d_in[8];
    const float* Wg_q  = (const float*)d_in[9];
    const float* bg_q  = (const float*)d_in[10];
    const float* W1    = (const float*)d_in[11];
    const float* b1    = (const float*)d_in[12];
    const float* W2    = (const float*)d_in[13];
    const float* b2    = (const float*)d_in[14];
    const float* Wa    = (const float*)d_in[15];
    const float* ba    = (const float*)d_in[16];
    float* out = (float*)d_out;

    prep_kernel<<<1, 512>>>(W1, b1, W2, b2);

    dim3 grid(BRD / BM, NCHUNK, 2);
    gemm_kernel<<<grid, 256>>>(hist, ques,
                               Wy_h, by_h, Wg_h, bg_h,
                               Wy_q, by_q, Wg_q, bg_q);

    final_kernel<<<(BRD + 255) / 256, 256>>>(noise, Wa, ba, out);
}

// round 2
// speedup vs baseline: 1.3397x; 1.3397x over previous
#include <cuda_runtime.h>
#include <math.h>

// Problem constants (B=1024, R=10, L=512)
#define BB   1024
#define RR   10
#define LL   512
#define KK   1024      // 2L
#define BRD  10240     // B*R

// GEMM tiling
#define BM 128
#define BN 128
#define BK 16
#define NCHUNK 8       // 512/64 l-values per block

// Scratch (static device memory; no allocation allowed)
__device__ float g_tpart[2][BRD][NCHUNK];  // per-row partial weighted sums
__device__ float g_wvec[2][LL];            // [0]=wh=W1[:L]@W2, [1]=wq=W1[L:]@W2
__device__ float g_c0;                     // b1.W2 + b2

// ---------------------------------------------------------------------------
// Prep: wh, wq, c0 — one warp per output, warp-shuffle reduction.
// grid = 256 blocks x 128 threads (4 warps) -> 1024 outputs.
// ---------------------------------------------------------------------------
__global__ __launch_bounds__(128)
void prep_kernel(const float* __restrict__ W1, const float* __restrict__ b1,
                 const float* __restrict__ W2, const float* __restrict__ b2)
{
    const int warp = threadIdx.x >> 5;
    const int lane = threadIdx.x & 31;
    const int idx  = blockIdx.x * 4 + warp;      // 0..1023 = row of W1

    float s = 0.f;
    #pragma unroll 4
    for (int m = lane; m < LL; m += 32)
        s += W1[(size_t)idx * LL + m] * W2[m];
    #pragma unroll
    for (int o = 16; o > 0; o >>= 1)
        s += __shfl_down_sync(0xFFFFFFFF, s, o);
    if (lane == 0) {
        if (idx < LL) g_wvec[0][idx] = s;
        else          g_wvec[1][idx - LL] = s;
    }

    // c0 computed by warp 0 of block 0
    if (blockIdx.x == 0 && warp == 0) {
        float c = 0.f;
        #pragma unroll 4
        for (int m = lane; m < LL; m += 32)
            c += b1[m] * W2[m];
        #pragma unroll
        for (int o = 16; o > 0; o >>= 1)
            c += __shfl_down_sync(0xFFFFFFFF, c, o);
        if (lane == 0) g_c0 = c + b2[0];
    }
}

// ---------------------------------------------------------------------------
// Packed f32x2 helpers
// ---------------------------------------------------------------------------
__device__ __forceinline__ unsigned long long bcast2(float x) {
    unsigned long long r;
    unsigned int xb = __float_as_uint(x);
    asm("mov.b64 %0, {%1, %1};" : "=l"(r) : "r"(xb));
    return r;
}
__device__ __forceinline__ void fma2(unsigned long long& d,
                                     unsigned long long a, unsigned long long b) {
    asm("fma.rn.f32x2 %0, %1, %2, %3;" : "=l"(d) : "l"(a), "l"(b), "l"(d));
}
__device__ __forceinline__ void unpack2(unsigned long long v, float& lo, float& hi) {
    unsigned int l, h;
    asm("mov.b64 {%0, %1}, %2;" : "=r"(l), "=r"(h) : "l"(v));
    lo = __uint_as_float(l);
    hi = __uint_as_float(h);
}

// ---------------------------------------------------------------------------
// Fused gated-transform GEMM + weighted reduction.
// Block: 128 rows x 64 l-values: u = X@Wy, v = X@Wg, then per-row
// sum of tanh(u+by)*sigmoid(v+bg)*w.  grid = (M/128, 512/64, 2 inputs)
// Mainloop uses packed f32x2 FMAs: accumulators paired along rows.
// ---------------------------------------------------------------------------
__global__ __launch_bounds__(256)
void gemm_kernel(const float* __restrict__ hist, const float* __restrict__ ques,
                 const float* __restrict__ Wy_h, const float* __restrict__ by_h,
                 const float* __restrict__ Wg_h, const float* __restrict__ bg_h,
                 const float* __restrict__ Wy_q, const float* __restrict__ by_q,
                 const float* __restrict__ Wg_q, const float* __restrict__ bg_q)
{
    __shared__ float As[BK][BM];
    __shared__ float Bs[BK][BN];

    const int input = blockIdx.z;
    const int l0    = blockIdx.y * 64;
    const int m0    = blockIdx.x * BM;

    const float* X  = input ? ques : hist;
    const float* Wy = input ? Wy_q : Wy_h;
    const float* Wg = input ? Wg_q : Wg_h;
    const float* by = input ? by_q : by_h;
    const float* bg = input ? bg_q : bg_h;

    const int tid = threadIdx.x;
    const int tx  = tid & 15;     // 0..15 (column group: 4 u-cols + 4 v-cols)
    const int ty  = tid >> 4;     // 0..15 (row group: 8 rows)

    // acc pairs: p = row-pair (rows ty*8+2p, ty*8+2p+1), j = 0..3 u-cols, 4..7 v-cols
    unsigned long long accp[4][8];
    #pragma unroll
    for (int p = 0; p < 4; p++)
        #pragma unroll
        for (int j = 0; j < 8; j++) accp[p][j] = 0ULL;

    for (int k0 = 0; k0 < KK; k0 += BK) {
        // ---- load X tile (transpose to As[k][m]) ----
        #pragma unroll
        for (int qq = 0; qq < 2; qq++) {
            int q   = tid * 2 + qq;       // 0..511
            int row = q >> 2;             // 0..127
            int kq  = q & 3;              // 0..3
            float4 v = *(const float4*)&X[(size_t)(m0 + row) * KK + k0 + kq * 4];
            As[kq * 4 + 0][row] = v.x;
            As[kq * 4 + 1][row] = v.y;
            As[kq * 4 + 2][row] = v.z;
            As[kq * 4 + 3][row] = v.w;
        }
        // ---- load weight tile: cols [0,64) Wy, cols [64,128) Wg ----
        #pragma unroll
        for (int qq = 0; qq < 2; qq++) {
            int q  = tid * 2 + qq;        // 0..511
            int k  = q >> 5;              // 0..15
            int j  = (q & 31) * 4;        // 0..124
            const float* src = (j < 64)
                ? &Wy[(size_t)(k0 + k) * LL + l0 + j]
                : &Wg[(size_t)(k0 + k) * LL + l0 + (j - 64)];
            *(float4*)&Bs[k][j] = *(const float4*)src;
        }
        __syncthreads();

        #pragma unroll
        for (int k = 0; k < BK; k++) {
            // A row-pairs: 4x LDS.64 of adjacent rows (8B-aligned)
            unsigned long long a2[4];
            const unsigned long long* ap =
                (const unsigned long long*)&As[k][ty * 8];
            a2[0] = ap[0]; a2[1] = ap[1]; a2[2] = ap[2]; a2[3] = ap[3];

            float bv[8];
            *(float4*)&bv[0] = *(const float4*)&Bs[k][tx * 4];        // u (Wy)
            *(float4*)&bv[4] = *(const float4*)&Bs[k][64 + tx * 4];   // v (Wg)
            unsigned long long b2[8];
            #pragma unroll
            for (int j = 0; j < 8; j++) b2[j] = bcast2(bv[j]);

            #pragma unroll
            for (int p = 0; p < 4; p++)
                #pragma unroll
                for (int j = 0; j < 8; j++)
                    fma2(accp[p][j], a2[p], b2[j]);
        }
        __syncthreads();
    }

    // ---- unpack ----
    float acc[8][8];
    #pragma unroll
    for (int p = 0; p < 4; p++)
        #pragma unroll
        for (int j = 0; j < 8; j++)
            unpack2(accp[p][j], acc[2 * p][j], acc[2 * p + 1][j]);

    // ---- epilogue: tanh(u+by)*sigmoid(v+bg)*w, partial over 4 l's ----
    const int gl = l0 + tx * 4;
    const float* w = g_wvec[input];
    float wv[4], byv[4], bgv[4];
    #pragma unroll
    for (int c = 0; c < 4; c++) {
        wv[c]  = w[gl + c];
        byv[c] = by[gl + c];
        bgv[c] = bg[gl + c];
    }
    float part[8];
    #pragma unroll
    for (int i = 0; i < 8; i++) {
        float s = 0.f;
        #pragma unroll
        for (int c = 0; c < 4; c++) {
            float u = acc[i][c]     + byv[c];
            float v = acc[i][4 + c] + bgv[c];
            s += tanhf(u) * (1.f / (1.f + expf(-v))) * wv[c];
        }
        part[i] = s;
    }

    // ---- deterministic cross-thread reduction (16 column-groups per row) ----
    float* red = &As[0][0];   // reuse smem (2048 floats)
    #pragma unroll
    for (int i = 0; i < 8; i++) red[tx * BM + ty * 8 + i] = part[i];
    __syncthreads();
    if (tx == 0) {
        #pragma unroll
        for (int i = 0; i < 8; i++) {
            float s = 0.f;
            #pragma unroll
            for (int x = 0; x < 16; x++) s += red[x * BM + ty * 8 + i];
            g_tpart[input][m0 + ty * 8 + i][blockIdx.y] = s;
        }
    }
}

// ---------------------------------------------------------------------------
// Final: logits + Gumbel, argmax over prefix, one-hot write.
// ---------------------------------------------------------------------------
__global__ void final_kernel(const float* __restrict__ noise,
                             const float* __restrict__ Wa, const float* __restrict__ ba,
                             float* __restrict__ out)
{
    int t = blockIdx.x * blockDim.x + threadIdx.x;
    if (t >= BRD) return;
    int b = t / RR;
    int i = t % RR;

    float Wa0 = Wa[0], Wa1 = Wa[1], ba0 = ba[0], c0 = g_c0;

    float tq = 0.f;
    #pragma unroll
    for (int c = 0; c < NCHUNK; c++) tq += g_tpart[1][t][c];

    float best = -3.4e38f;
    int bj = 0;
    for (int j = 0; j <= i; j++) {
        float th = 0.f;
        #pragma unroll
        for (int c = 0; c < NCHUNK; c++) th += g_tpart[0][b * RR + j][c];
        float score = tq + th + c0;
        float logit = score * Wa0 + (float)(i - j + 1) * Wa1 + ba0;
        float ns = noise[(size_t)b * RR * RR + i * RR + j];
        float g  = -logf(1e-10f - logf(ns + 1e-10f));
        float z  = logit + g;
        if (z > best) { best = z; bj = j; }   // strict > keeps first max
    }

    float* o = out + (size_t)b * RR * RR + (size_t)i * RR;
    #pragma unroll
    for (int j = 0; j < RR; j++) o[j] = (j == bj) ? 1.f : 0.f;
}

// ---------------------------------------------------------------------------
extern "C" void kernel_launch(void* const* d_in, const int* in_sizes, int n_in,
                              void* d_out, int out_size)
{
    const float* hist  = (const float*)d_in[0];
    const float* ques  = (const float*)d_in[1];
    const float* noise = (const float*)d_in[2];
    const float* Wy_h  = (const float*)d_in[3];
    const float* by_h  = (const float*)d_in[4];
    const float* Wg_h  = (const float*)d_in[5];
    const float* bg_h  = (const float*)d_in[6];
    const float* Wy_q  = (const float*)d_in[7];
    const float* by_q  = (const float*)d_in[8];
    const float* Wg_q  = (const float*)d_in[9];
    const float* bg_q  = (const float*)d_in[10];
    const float* W1    = (const float*)d_in[11];
    const float* b1    = (const float*)d_in[12];
    const float* W2    = (const float*)d_in[13];
    const float* b2    = (const float*)d_in[14];
    const float* Wa    = (const float*)d_in[15];
    const float* ba    = (const float*)d_in[16];
    float* out = (float*)d_out;

    prep_kernel<<<256, 128>>>(W1, b1, W2, b2);

    dim3 grid(BRD / BM, NCHUNK, 2);
    gemm_kernel<<<grid, 256>>>(hist, ques,
                               Wy_h, by_h, Wg_h, bg_h,
                               Wy_q, by_q, Wg_q, bg_q);

    final_kernel<<<(BRD + 255) / 256, 256>>>(noise, Wa, ba, out);
}